// round 16
// baseline (speedup 1.0000x reference)
#include <cuda_runtime.h>

// 4-level 2D Haar DWT, fully fused, register-level level-0 (R2 config) with
// WARP-ROTATED SUBBAND STORE ORDER at level 0: warp w issues its 4 subband
// stores starting at subband (w&3), de-phasing the four 50MB write streams so
// all four output regions receive traffic simultaneously (better DRAM bank-
// level parallelism) instead of machine-wide lockstep cA->cH->cV->cD bursts.
// Addresses/values unchanged; only per-warp issue order differs.
//
// Input : x (64, 3, 512, 512) f32 -> 192 images of 512x512
// Output: concat of levels l=0..3, each (192, 4, S, S), S = 256 >> l
//   subband order: 0=cA, 1=cH, 2=cV, 3=cD
// Block = 256 threads, tile = 64x64 input. Grid: (8, 8, 192).

#define NIMG 192
#define HW   512

#define OFF0 0ull
#define OFF1 (OFF0 + (unsigned long long)NIMG * 4ull * 256ull * 256ull)
#define OFF2 (OFF1 + (unsigned long long)NIMG * 4ull * 128ull * 128ull)
#define OFF3 (OFF2 + (unsigned long long)NIMG * 4ull *  64ull *  64ull)

#define HAAR(a, b, c, d, cA, cH, cV, cD)                    \
    do {                                                    \
        float _hs0 = (a) + (b), _hd0 = (a) - (b);           \
        float _hs1 = (c) + (d), _hd1 = (c) - (d);           \
        (cA) = (_hs0 + _hs1) * 0.5f;                        \
        (cH) = (_hs0 - _hs1) * 0.5f;                        \
        (cV) = (_hd0 + _hd1) * 0.5f;                        \
        (cD) = (_hd0 - _hd1) * 0.5f;                        \
    } while (0)

__global__ __launch_bounds__(256) void fwt_kernel(const float* __restrict__ x,
                                                  float* __restrict__ out) {
    const int img = blockIdx.z;
    const int ty  = blockIdx.y;
    const int tx  = blockIdx.x;
    const int tid = threadIdx.x;

    __shared__ float sB[32][33];  // level-0 cA
    __shared__ float sC[16][17];  // level-1 cA
    __shared__ float sD[8][9];    // level-2 cA

    // ---- level 0: direct global -> registers -> global, S=256 ----
    {
        const int qi  = tid >> 3;   // 0..31 quad row
        const int qjg = tid & 7;    // group of 4 quads -> input cols qjg*8..+7

        const float* src = x + ((size_t)img * HW + (size_t)ty * 64 + 2 * qi) * HW
                             + (size_t)tx * 64 + qjg * 8;
        const float4 r0a = *reinterpret_cast<const float4*>(src);
        const float4 r0b = *reinterpret_cast<const float4*>(src + 4);
        const float4 r1a = *reinterpret_cast<const float4*>(src + HW);
        const float4 r1b = *reinterpret_cast<const float4*>(src + HW + 4);

        float4 cA4, cH4, cV4, cD4;
        HAAR(r0a.x, r0a.y, r1a.x, r1a.y, cA4.x, cH4.x, cV4.x, cD4.x);
        HAAR(r0a.z, r0a.w, r1a.z, r1a.w, cA4.y, cH4.y, cV4.y, cD4.y);
        HAAR(r0b.x, r0b.y, r1b.x, r1b.y, cA4.z, cH4.z, cV4.z, cD4.z);
        HAAR(r0b.z, r0b.w, r1b.z, r1b.w, cA4.w, cH4.w, cV4.w, cD4.w);

        const int S = 256;
        float* base = out + OFF0 + (size_t)img * 4ull * S * S;
        const int gi = ty * 32 + qi, gj = tx * 32 + qjg * 4;
        const size_t o = (size_t)gi * S + gj;

        float4* pA = reinterpret_cast<float4*>(base + o);
        float4* pH = reinterpret_cast<float4*>(base + (size_t)S * S + o);
        float4* pV = reinterpret_cast<float4*>(base + 2ull * S * S + o);
        float4* pD = reinterpret_cast<float4*>(base + 3ull * S * S + o);

        // rotate store issue order by warp: de-phase the 4 write streams
        switch ((tid >> 5) & 3) {
            case 0: *pA = cA4; *pH = cH4; *pV = cV4; *pD = cD4; break;
            case 1: *pH = cH4; *pV = cV4; *pD = cD4; *pA = cA4; break;
            case 2: *pV = cV4; *pD = cD4; *pA = cA4; *pH = cH4; break;
            default:*pD = cD4; *pA = cA4; *pH = cH4; *pV = cV4; break;
        }

        sB[qi][qjg * 4 + 0] = cA4.x;
        sB[qi][qjg * 4 + 1] = cA4.y;
        sB[qi][qjg * 4 + 2] = cA4.z;
        sB[qi][qjg * 4 + 3] = cA4.w;
    }
    __syncthreads();

    // ---- level 1: 32x32 -> 16x16, S=128 (64 threads x 4 quads) ----
    if (tid < 64) {
        const int qi  = tid >> 2;   // 0..15
        const int qjg = tid & 3;    // cols qjg*8..+7 of sB

        float4 cA4, cH4, cV4, cD4;
        {
            const int r0 = 2 * qi, r1 = 2 * qi + 1, c0 = qjg * 8;
            HAAR(sB[r0][c0 + 0], sB[r0][c0 + 1], sB[r1][c0 + 0], sB[r1][c0 + 1],
                 cA4.x, cH4.x, cV4.x, cD4.x);
            HAAR(sB[r0][c0 + 2], sB[r0][c0 + 3], sB[r1][c0 + 2], sB[r1][c0 + 3],
                 cA4.y, cH4.y, cV4.y, cD4.y);
            HAAR(sB[r0][c0 + 4], sB[r0][c0 + 5], sB[r1][c0 + 4], sB[r1][c0 + 5],
                 cA4.z, cH4.z, cV4.z, cD4.z);
            HAAR(sB[r0][c0 + 6], sB[r0][c0 + 7], sB[r1][c0 + 6], sB[r1][c0 + 7],
                 cA4.w, cH4.w, cV4.w, cD4.w);
        }

        const int S = 128;
        float* base = out + OFF1 + (size_t)img * 4ull * S * S;
        const int gi = ty * 16 + qi, gj = tx * 16 + qjg * 4;
        const size_t o = (size_t)gi * S + gj;
        *reinterpret_cast<float4*>(base + o)                 = cA4;
        *reinterpret_cast<float4*>(base + (size_t)S * S + o) = cH4;
        *reinterpret_cast<float4*>(base + 2ull * S * S + o)  = cV4;
        *reinterpret_cast<float4*>(base + 3ull * S * S + o)  = cD4;

        sC[qi][qjg * 4 + 0] = cA4.x;
        sC[qi][qjg * 4 + 1] = cA4.y;
        sC[qi][qjg * 4 + 2] = cA4.z;
        sC[qi][qjg * 4 + 3] = cA4.w;
    }
    __syncthreads();

    // ---- level 2: 16x16 -> 8x8, S=64 (16 threads x 4 quads) ----
    if (tid < 16) {
        const int qi  = tid >> 1;   // 0..7
        const int qjg = tid & 1;    // cols qjg*8..+7 of sC

        float4 cA4, cH4, cV4, cD4;
        {
            const int r0 = 2 * qi, r1 = 2 * qi + 1, c0 = qjg * 8;
            HAAR(sC[r0][c0 + 0], sC[r0][c0 + 1], sC[r1][c0 + 0], sC[r1][c0 + 1],
                 cA4.x, cH4.x, cV4.x, cD4.x);
            HAAR(sC[r0][c0 + 2], sC[r0][c0 + 3], sC[r1][c0 + 2], sC[r1][c0 + 3],
                 cA4.y, cH4.y, cV4.y, cD4.y);
            HAAR(sC[r0][c0 + 4], sC[r0][c0 + 5], sC[r1][c0 + 4], sC[r1][c0 + 5],
                 cA4.z, cH4.z, cV4.z, cD4.z);
            HAAR(sC[r0][c0 + 6], sC[r0][c0 + 7], sC[r1][c0 + 6], sC[r1][c0 + 7],
                 cA4.w, cH4.w, cV4.w, cD4.w);
        }

        const int S = 64;
        float* base = out + OFF2 + (size_t)img * 4ull * S * S;
        const int gi = ty * 8 + qi, gj = tx * 8 + qjg * 4;
        const size_t o = (size_t)gi * S + gj;
        *reinterpret_cast<float4*>(base + o)                 = cA4;
        *reinterpret_cast<float4*>(base + (size_t)S * S + o) = cH4;
        *reinterpret_cast<float4*>(base + 2ull * S * S + o)  = cV4;
        *reinterpret_cast<float4*>(base + 3ull * S * S + o)  = cD4;

        sD[qi][qjg * 4 + 0] = cA4.x;
        sD[qi][qjg * 4 + 1] = cA4.y;
        sD[qi][qjg * 4 + 2] = cA4.z;
        sD[qi][qjg * 4 + 3] = cA4.w;
    }
    __syncthreads();

    // ---- level 3: 8x8 -> 4x4, S=32 (4 threads x 4 quads) ----
    if (tid < 4) {
        const int qi = tid;  // 0..3, full 4-quad row

        float4 cA4, cH4, cV4, cD4;
        {
            const int r0 = 2 * qi, r1 = 2 * qi + 1;
            HAAR(sD[r0][0], sD[r0][1], sD[r1][0], sD[r1][1], cA4.x, cH4.x, cV4.x, cD4.x);
            HAAR(sD[r0][2], sD[r0][3], sD[r1][2], sD[r1][3], cA4.y, cH4.y, cV4.y, cD4.y);
            HAAR(sD[r0][4], sD[r0][5], sD[r1][4], sD[r1][5], cA4.z, cH4.z, cV4.z, cD4.z);
            HAAR(sD[r0][6], sD[r0][7], sD[r1][6], sD[r1][7], cA4.w, cH4.w, cV4.w, cD4.w);
        }

        const int S = 32;
        float* base = out + OFF3 + (size_t)img * 4ull * S * S;
        const int gi = ty * 4 + qi, gj = tx * 4;
        const size_t o = (size_t)gi * S + gj;
        *reinterpret_cast<float4*>(base + o)                 = cA4;
        *reinterpret_cast<float4*>(base + (size_t)S * S + o) = cH4;
        *reinterpret_cast<float4*>(base + 2ull * S * S + o)  = cV4;
        *reinterpret_cast<float4*>(base + 3ull * S * S + o)  = cD4;
    }
}

extern "C" void kernel_launch(void* const* d_in, const int* in_sizes, int n_in,
                              void* d_out, int out_size) {
    const float* x = (const float*)d_in[0];
    float* out     = (float*)d_out;
    dim3 grid(8, 8, NIMG);
    fwt_kernel<<<grid, 256>>>(x, out);
}

// round 17
// speedup vs baseline: 1.0213x; 1.0213x over previous
#include <cuda_runtime.h>

// FINAL (locked): 4-level 2D Haar DWT, fully fused, register-level level-0.
// Best measured config across 10 rounds: 72.2us wall best / 66.3us ncu,
// DRAM=77.5-79.0%, ~6.2 TB/s = practical mixed R/W HBM3e ceiling (~78% spec).
// Exhausted levers (all neutral or regressions): cache hints (2x2 matrix),
// tile shapes (128x64, 64x128), persistent grid, tail widths, lane remaps,
// warp-rotated store order. Traffic is mandatory: 201MB read + 267MB write.
//
// Input : x (64, 3, 512, 512) f32 -> 192 images of 512x512
// Output: concat of levels l=0..3, each (192, 4, S, S), S = 256 >> l
//   subband order: 0=cA, 1=cH, 2=cV, 3=cD
// Block = 256 threads, tile = 64x64 input. Grid: (8, 8, 192).

#define NIMG 192
#define HW   512

#define OFF0 0ull
#define OFF1 (OFF0 + (unsigned long long)NIMG * 4ull * 256ull * 256ull)
#define OFF2 (OFF1 + (unsigned long long)NIMG * 4ull * 128ull * 128ull)
#define OFF3 (OFF2 + (unsigned long long)NIMG * 4ull *  64ull *  64ull)

#define HAAR(a, b, c, d, cA, cH, cV, cD)                    \
    do {                                                    \
        float _hs0 = (a) + (b), _hd0 = (a) - (b);           \
        float _hs1 = (c) + (d), _hd1 = (c) - (d);           \
        (cA) = (_hs0 + _hs1) * 0.5f;                        \
        (cH) = (_hs0 - _hs1) * 0.5f;                        \
        (cV) = (_hd0 + _hd1) * 0.5f;                        \
        (cD) = (_hd0 - _hd1) * 0.5f;                        \
    } while (0)

__global__ __launch_bounds__(256) void fwt_kernel(const float* __restrict__ x,
                                                  float* __restrict__ out) {
    const int img = blockIdx.z;
    const int ty  = blockIdx.y;
    const int tx  = blockIdx.x;
    const int tid = threadIdx.x;

    __shared__ float sB[32][33];  // level-0 cA
    __shared__ float sC[16][17];  // level-1 cA
    __shared__ float sD[8][9];    // level-2 cA

    // ---- level 0: direct global -> registers -> global, S=256 ----
    {
        const int qi  = tid >> 3;   // 0..31 quad row
        const int qjg = tid & 7;    // group of 4 quads -> input cols qjg*8..+7

        const float* src = x + ((size_t)img * HW + (size_t)ty * 64 + 2 * qi) * HW
                             + (size_t)tx * 64 + qjg * 8;
        const float4 r0a = *reinterpret_cast<const float4*>(src);
        const float4 r0b = *reinterpret_cast<const float4*>(src + 4);
        const float4 r1a = *reinterpret_cast<const float4*>(src + HW);
        const float4 r1b = *reinterpret_cast<const float4*>(src + HW + 4);

        float4 cA4, cH4, cV4, cD4;
        HAAR(r0a.x, r0a.y, r1a.x, r1a.y, cA4.x, cH4.x, cV4.x, cD4.x);
        HAAR(r0a.z, r0a.w, r1a.z, r1a.w, cA4.y, cH4.y, cV4.y, cD4.y);
        HAAR(r0b.x, r0b.y, r1b.x, r1b.y, cA4.z, cH4.z, cV4.z, cD4.z);
        HAAR(r0b.z, r0b.w, r1b.z, r1b.w, cA4.w, cH4.w, cV4.w, cD4.w);

        const int S = 256;
        float* base = out + OFF0 + (size_t)img * 4ull * S * S;
        const int gi = ty * 32 + qi, gj = tx * 32 + qjg * 4;
        const size_t o = (size_t)gi * S + gj;
        *reinterpret_cast<float4*>(base + o)                 = cA4;
        *reinterpret_cast<float4*>(base + (size_t)S * S + o) = cH4;
        *reinterpret_cast<float4*>(base + 2ull * S * S + o)  = cV4;
        *reinterpret_cast<float4*>(base + 3ull * S * S + o)  = cD4;

        sB[qi][qjg * 4 + 0] = cA4.x;
        sB[qi][qjg * 4 + 1] = cA4.y;
        sB[qi][qjg * 4 + 2] = cA4.z;
        sB[qi][qjg * 4 + 3] = cA4.w;
    }
    __syncthreads();

    // ---- level 1: 32x32 -> 16x16, S=128 (64 threads x 4 quads) ----
    if (tid < 64) {
        const int qi  = tid >> 2;   // 0..15
        const int qjg = tid & 3;    // cols qjg*8..+7 of sB

        float4 cA4, cH4, cV4, cD4;
        {
            const int r0 = 2 * qi, r1 = 2 * qi + 1, c0 = qjg * 8;
            HAAR(sB[r0][c0 + 0], sB[r0][c0 + 1], sB[r1][c0 + 0], sB[r1][c0 + 1],
                 cA4.x, cH4.x, cV4.x, cD4.x);
            HAAR(sB[r0][c0 + 2], sB[r0][c0 + 3], sB[r1][c0 + 2], sB[r1][c0 + 3],
                 cA4.y, cH4.y, cV4.y, cD4.y);
            HAAR(sB[r0][c0 + 4], sB[r0][c0 + 5], sB[r1][c0 + 4], sB[r1][c0 + 5],
                 cA4.z, cH4.z, cV4.z, cD4.z);
            HAAR(sB[r0][c0 + 6], sB[r0][c0 + 7], sB[r1][c0 + 6], sB[r1][c0 + 7],
                 cA4.w, cH4.w, cV4.w, cD4.w);
        }

        const int S = 128;
        float* base = out + OFF1 + (size_t)img * 4ull * S * S;
        const int gi = ty * 16 + qi, gj = tx * 16 + qjg * 4;
        const size_t o = (size_t)gi * S + gj;
        *reinterpret_cast<float4*>(base + o)                 = cA4;
        *reinterpret_cast<float4*>(base + (size_t)S * S + o) = cH4;
        *reinterpret_cast<float4*>(base + 2ull * S * S + o)  = cV4;
        *reinterpret_cast<float4*>(base + 3ull * S * S + o)  = cD4;

        sC[qi][qjg * 4 + 0] = cA4.x;
        sC[qi][qjg * 4 + 1] = cA4.y;
        sC[qi][qjg * 4 + 2] = cA4.z;
        sC[qi][qjg * 4 + 3] = cA4.w;
    }
    __syncthreads();

    // ---- level 2: 16x16 -> 8x8, S=64 (16 threads x 4 quads) ----
    if (tid < 16) {
        const int qi  = tid >> 1;   // 0..7
        const int qjg = tid & 1;    // cols qjg*8..+7 of sC

        float4 cA4, cH4, cV4, cD4;
        {
            const int r0 = 2 * qi, r1 = 2 * qi + 1, c0 = qjg * 8;
            HAAR(sC[r0][c0 + 0], sC[r0][c0 + 1], sC[r1][c0 + 0], sC[r1][c0 + 1],
                 cA4.x, cH4.x, cV4.x, cD4.x);
            HAAR(sC[r0][c0 + 2], sC[r0][c0 + 3], sC[r1][c0 + 2], sC[r1][c0 + 3],
                 cA4.y, cH4.y, cV4.y, cD4.y);
            HAAR(sC[r0][c0 + 4], sC[r0][c0 + 5], sC[r1][c0 + 4], sC[r1][c0 + 5],
                 cA4.z, cH4.z, cV4.z, cD4.z);
            HAAR(sC[r0][c0 + 6], sC[r0][c0 + 7], sC[r1][c0 + 6], sC[r1][c0 + 7],
                 cA4.w, cH4.w, cV4.w, cD4.w);
        }

        const int S = 64;
        float* base = out + OFF2 + (size_t)img * 4ull * S * S;
        const int gi = ty * 8 + qi, gj = tx * 8 + qjg * 4;
        const size_t o = (size_t)gi * S + gj;
        *reinterpret_cast<float4*>(base + o)                 = cA4;
        *reinterpret_cast<float4*>(base + (size_t)S * S + o) = cH4;
        *reinterpret_cast<float4*>(base + 2ull * S * S + o)  = cV4;
        *reinterpret_cast<float4*>(base + 3ull * S * S + o)  = cD4;

        sD[qi][qjg * 4 + 0] = cA4.x;
        sD[qi][qjg * 4 + 1] = cA4.y;
        sD[qi][qjg * 4 + 2] = cA4.z;
        sD[qi][qjg * 4 + 3] = cA4.w;
    }
    __syncthreads();

    // ---- level 3: 8x8 -> 4x4, S=32 (4 threads x 4 quads) ----
    if (tid < 4) {
        const int qi = tid;  // 0..3, full 4-quad row

        float4 cA4, cH4, cV4, cD4;
        {
            const int r0 = 2 * qi, r1 = 2 * qi + 1;
            HAAR(sD[r0][0], sD[r0][1], sD[r1][0], sD[r1][1], cA4.x, cH4.x, cV4.x, cD4.x);
            HAAR(sD[r0][2], sD[r0][3], sD[r1][2], sD[r1][3], cA4.y, cH4.y, cV4.y, cD4.y);
            HAAR(sD[r0][4], sD[r0][5], sD[r1][4], sD[r1][5], cA4.z, cH4.z, cV4.z, cD4.z);
            HAAR(sD[r0][6], sD[r0][7], sD[r1][6], sD[r1][7], cA4.w, cH4.w, cV4.w, cD4.w);
        }

        const int S = 32;
        float* base = out + OFF3 + (size_t)img * 4ull * S * S;
        const int gi = ty * 4 + qi, gj = tx * 4;
        const size_t o = (size_t)gi * S + gj;
        *reinterpret_cast<float4*>(base + o)                 = cA4;
        *reinterpret_cast<float4*>(base + (size_t)S * S + o) = cH4;
        *reinterpret_cast<float4*>(base + 2ull * S * S + o)  = cV4;
        *reinterpret_cast<float4*>(base + 3ull * S * S + o)  = cD4;
    }
}

extern "C" void kernel_launch(void* const* d_in, const int* in_sizes, int n_in,
                              void* d_out, int out_size) {
    const float* x = (const float*)d_in[0];
    float* out     = (float*)d_out;
    dim3 grid(8, 8, NIMG);
    fwt_kernel<<<grid, 256>>>(x, out);
}